// round 13
// baseline (speedup 1.0000x reference)
#include <cuda_runtime.h>
#include <cstdint>

// out[r][c] = in[2r+1][2c+1], in: 8192x8192 f32, out: 4096x4096 f32.
//
// Steady-state record config (R11: 31.26 us) — re-bench for confirmation.
//
// DRAM-bound at the ~6 TB/s mixed read+write HBM ceiling. Settled R1-R12:
//  - 2 output rows per thread (MLP_p1=4) is the harness steady-state
//    optimum (1 row and 4 rows: ~33 us; v8 width: 33.2 us).
//  - default load AND store policy (all cache hints neutral or regressive).
//  - float4 accesses, block=256, grid=8192.

static constexpr int N_IN  = 8192;
static constexpr int N_OUT = 4096;
static constexpr int VECS_PER_ROW = N_OUT / 4;   // 1024 float4 per output row
static constexpr int IN_ROW_V4    = N_IN / 4;    // 2048 float4 per input row
static constexpr int ROWS_PER_THREAD = 2;

__global__ void downsample2x_kernel(const float4* __restrict__ in,
                                    float4* __restrict__ out) {
    unsigned tid = blockIdx.x * blockDim.x + threadIdx.x;  // 0 .. 2,097,151
    unsigned vec = tid & (VECS_PER_ROW - 1);               // 0..1023
    unsigned rg  = tid >> 10;                              // row group 0..2047

    // Output rows 2rg, 2rg+1  <-  input rows 4rg+1, 4rg+3.
    const float4* p = in + (size_t)(4u * rg + 1u) * IN_ROW_V4 + 2u * vec;

    // Front-batched default-policy loads (4 independent LDG.128).
    float4 a0 = p[0];
    float4 b0 = p[1];
    float4 a1 = p[2 * IN_ROW_V4];
    float4 b1 = p[2 * IN_ROW_V4 + 1];

    float4* q = out + (size_t)(2u * rg) * VECS_PER_ROW + vec;

    q[0]            = make_float4(a0.y, a0.w, b0.y, b0.w);
    q[VECS_PER_ROW] = make_float4(a1.y, a1.w, b1.y, b1.w);
}

extern "C" void kernel_launch(void* const* d_in, const int* in_sizes, int n_in,
                              void* d_out, int out_size) {
    const float4* in  = (const float4*)d_in[0];
    float4*       out = (float4*)d_out;

    const int total_threads = (N_OUT / ROWS_PER_THREAD) * VECS_PER_ROW; // 2,097,152
    const int block = 256;
    const int grid  = total_threads / block;                            // 8192

    downsample2x_kernel<<<grid, block>>>(in, out);
}

// round 14
// speedup vs baseline: 1.0068x; 1.0068x over previous
#include <cuda_runtime.h>
#include <cstdint>

// out[r][c] = in[2r+1][2c+1], in: 8192x8192 f32, out: 4096x4096 f32.
//
// Third sample of the R11 config (samples so far: 31.26 us healthy run,
// 37.63 us degraded run — R13's profile showed DRAM 59% on identical SASS,
// i.e. environment, not kernel). Decision: <=33 -> final; >34 -> fall back
// to the 1-row/thread config.
//
// DRAM-bound at the ~6 TB/s mixed read+write HBM ceiling. 2 output rows
// per thread (MLP_p1=4), float4 accesses, default load+store policy,
// block=256, grid=8192.

static constexpr int N_IN  = 8192;
static constexpr int N_OUT = 4096;
static constexpr int VECS_PER_ROW = N_OUT / 4;   // 1024 float4 per output row
static constexpr int IN_ROW_V4    = N_IN / 4;    // 2048 float4 per input row
static constexpr int ROWS_PER_THREAD = 2;

__global__ void downsample2x_kernel(const float4* __restrict__ in,
                                    float4* __restrict__ out) {
    unsigned tid = blockIdx.x * blockDim.x + threadIdx.x;  // 0 .. 2,097,151
    unsigned vec = tid & (VECS_PER_ROW - 1);               // 0..1023
    unsigned rg  = tid >> 10;                              // row group 0..2047

    // Output rows 2rg, 2rg+1  <-  input rows 4rg+1, 4rg+3.
    const float4* p = in + (size_t)(4u * rg + 1u) * IN_ROW_V4 + 2u * vec;

    // Front-batched default-policy loads (4 independent LDG.128).
    float4 a0 = p[0];
    float4 b0 = p[1];
    float4 a1 = p[2 * IN_ROW_V4];
    float4 b1 = p[2 * IN_ROW_V4 + 1];

    float4* q = out + (size_t)(2u * rg) * VECS_PER_ROW + vec;

    q[0]            = make_float4(a0.y, a0.w, b0.y, b0.w);
    q[VECS_PER_ROW] = make_float4(a1.y, a1.w, b1.y, b1.w);
}

extern "C" void kernel_launch(void* const* d_in, const int* in_sizes, int n_in,
                              void* d_out, int out_size) {
    const float4* in  = (const float4*)d_in[0];
    float4*       out = (float4*)d_out;

    const int total_threads = (N_OUT / ROWS_PER_THREAD) * VECS_PER_ROW; // 2,097,152
    const int block = 256;
    const int grid  = total_threads / block;                            // 8192

    downsample2x_kernel<<<grid, block>>>(in, out);
}

// round 15
// speedup vs baseline: 1.1232x; 1.1156x over previous
#include <cuda_runtime.h>
#include <cstdint>

// out[r][c] = in[2r+1][2c+1], in: 8192x8192 f32, out: 4096x4096 f32.
//
// FINAL: 1 float4 per thread, default load+store policy, block=256.
// Sample history: {32.83, 33.28, 33.28} us — the tightest and best-EV
// config. The 2-rows/thread variant sampled {31.26, 37.63, 37.38}
// (bimodal; bad runs show DRAM 59%/L1 83% on identical SASS — likely
// allocation-dependent L2-die/channel hash interaction with its paired
// odd-row access pattern). All configs are DRAM-bound at the ~6 TB/s
// mixed read+write HBM ceiling on healthy runs (75-77% of spec);
// traffic floor = 128 MB read (every 32B sector of odd rows is needed)
// + 64 MB write.

static constexpr int N_IN  = 8192;
static constexpr int N_OUT = 4096;
static constexpr int VECS_PER_ROW = N_OUT / 4;   // 1024 float4 per output row
static constexpr int IN_ROW_V4    = N_IN / 4;    // 2048 float4 per input row

__global__ void downsample2x_kernel(const float4* __restrict__ in,
                                    float4* __restrict__ out) {
    unsigned tid = blockIdx.x * blockDim.x + threadIdx.x;   // 0 .. 4,194,303
    unsigned row = tid >> 10;          // / VECS_PER_ROW
    unsigned vec = tid & 1023;         // % VECS_PER_ROW

    const float4* in_row = in + (size_t)(2u * row + 1u) * IN_ROW_V4;

    float4 a = in_row[2u * vec];
    float4 b = in_row[2u * vec + 1u];

    float4 o;
    o.x = a.y;
    o.y = a.w;
    o.z = b.y;
    o.w = b.w;

    out[(size_t)row * VECS_PER_ROW + vec] = o;
}

extern "C" void kernel_launch(void* const* d_in, const int* in_sizes, int n_in,
                              void* d_out, int out_size) {
    const float4* in  = (const float4*)d_in[0];
    float4*       out = (float4*)d_out;

    const int total_threads = N_OUT * VECS_PER_ROW;  // 4,194,304
    const int block = 256;
    const int grid  = total_threads / block;         // 16384

    downsample2x_kernel<<<grid, block>>>(in, out);
}

// round 16
// speedup vs baseline: 1.1451x; 1.0195x over previous
#include <cuda_runtime.h>
#include <cstdint>

// out[r][c] = in[2r+1][2c+1], in: 8192x8192 f32, out: 4096x4096 f32.
//
// Final form (1 float4 per thread, default load+store policy), sampling
// the last untested knob: block=128 (32768 CTAs, finer wave granularity,
// more independent CTA streams per SM).
//
// DRAM-bound at the ~6 TB/s mixed read+write HBM ceiling (75-77% of spec
// on healthy runs). Traffic floor: 128 MB read (every 32B sector of odd
// rows carries needed odd columns) + 64 MB write. Settled R1-R15:
// default cache policy everywhere; float4 width; 1 row/thread is the
// stable optimum ({32.83, 33.28, 33.28, 33.50} us).

static constexpr int N_IN  = 8192;
static constexpr int N_OUT = 4096;
static constexpr int VECS_PER_ROW = N_OUT / 4;   // 1024 float4 per output row
static constexpr int IN_ROW_V4    = N_IN / 4;    // 2048 float4 per input row

__global__ void downsample2x_kernel(const float4* __restrict__ in,
                                    float4* __restrict__ out) {
    unsigned tid = blockIdx.x * blockDim.x + threadIdx.x;   // 0 .. 4,194,303
    unsigned row = tid >> 10;          // / VECS_PER_ROW
    unsigned vec = tid & 1023;         // % VECS_PER_ROW

    const float4* in_row = in + (size_t)(2u * row + 1u) * IN_ROW_V4;

    float4 a = in_row[2u * vec];
    float4 b = in_row[2u * vec + 1u];

    float4 o;
    o.x = a.y;
    o.y = a.w;
    o.z = b.y;
    o.w = b.w;

    out[(size_t)row * VECS_PER_ROW + vec] = o;
}

extern "C" void kernel_launch(void* const* d_in, const int* in_sizes, int n_in,
                              void* d_out, int out_size) {
    const float4* in  = (const float4*)d_in[0];
    float4*       out = (float4*)d_out;

    const int total_threads = N_OUT * VECS_PER_ROW;  // 4,194,304
    const int block = 128;
    const int grid  = total_threads / block;         // 32768

    downsample2x_kernel<<<grid, block>>>(in, out);
}